// round 8
// baseline (speedup 1.0000x reference)
#include <cuda_runtime.h>

#define LVLS 16
#define TSIZE 16384
#define NPTS 262144
#define TMASK 16383
#define PRIME1 (-1640531535)   // 2654435761 wrapped to int32
#define PRIME2 (805459861)
#define CTAS_PER_LVL 9
#define NTHREADS 1024
#define NCHUNK 4
#define CHPTS (NPTS / NCHUNK)  // 65536 points per pipeline chunk
#define TPTS 512               // points per transpose tile
#define TTHREADS 256           // transpose block size (2 points/thread)
#define TPITCH (TPTS + 2)      // float2 pitch: 514 -> 4112B rows, 16B aligned

// Scratch in (L, N) layout of float2 — 33.5MB static device array (allowed).
__device__ float2 g_scr[(size_t)LVLS * NPTS];

// ---------------------------------------------------------------------------
// Kernel 1: hash-grid gather for one point-chunk. One CTA per (level, slice);
// the level's 128KB table lives in shared memory. Stores go to scratch in
// (L,N,2) layout so each warp-store is 256B contiguous.
// ---------------------------------------------------------------------------
__global__ __launch_bounds__(NTHREADS, 1)
void hash_enc_kernel(const float* __restrict__ x,
                     const float* __restrict__ emb,
                     int nbase)
{
    extern __shared__ float2 table[];   // TSIZE float2 = 128KB
    const int level = blockIdx.y;

    // Cooperative table load (float4-vectorized, coalesced)
    {
        const float4* src = (const float4*)(emb + (size_t)level * TSIZE * 2);
        float4* dst = (float4*)table;
        #pragma unroll
        for (int i = threadIdx.x; i < (TSIZE * 2) / 4; i += NTHREADS)
            dst[i] = src[i];
    }
    __syncthreads();

    // Per-level resolution: N_l = Nmin * b^l  (identical formula to the
    // passing kernel — do not perturb index-determining arithmetic)
    const float bgrow = expf((logf(512.0f) - logf(16.0f)) * (1.0f / 16.0f));
    const float scale = 16.0f * powf(bgrow, (float)level);

    float2* scr = g_scr + (size_t)level * NPTS;

    const int nend = nbase + CHPTS;
    const int stride = CTAS_PER_LVL * NTHREADS;
    for (int n = nbase + blockIdx.x * NTHREADS + threadIdx.x; n < nend; n += stride) {
        const float x0 = x[n * 3 + 0];
        const float x1 = x[n * 3 + 1];
        const float x2 = x[n * 3 + 2];

        const float u0 = x0 * scale, u1 = x1 * scale, u2 = x2 * scale;
        const float f0 = floorf(u0), f1 = floorf(u1), f2 = floorf(u2);
        const int   i0 = (int)f0,    i1 = (int)f1,    i2 = (int)f2;
        // d = ceil-floor is 1 when frac>0, else 0 -> diff == frac either way.
        const float d0 = u0 - f0, d1 = u1 - f1, d2 = u2 - f2;
        const float o0 = 1.0f - d0, o1 = 1.0f - d1, o2 = 1.0f - d2;

        // Pre-multiplied corner hash terms (wrapping int32, matches jnp/torch)
        const int pl0 = i0;                  const int ph0 = pl0 + 1;
        const int pl1 = i1 * PRIME1;         const int ph1 = pl1 + PRIME1;
        const int pl2 = i2 * PRIME2;         const int ph2 = pl2 + PRIME2;
        // frac==0 corners carry an exactly-zero weight, so hi = lo+1 is safe.

        float ax = 0.0f, ay = 0.0f;
        #pragma unroll
        for (int k = 0; k < 8; ++k) {
            const int a = (k >> 2) & 1;     // dim0
            const int b = (k >> 1) & 1;     // dim1
            const int c = k & 1;            // dim2
            const int h = (a ? ph0 : pl0) ^ (b ? ph1 : pl1) ^ (c ? ph2 : pl2);
            const int idx = h & TMASK;      // == mod 16384 for int32
            const float w = (a ? d0 : o0) * (b ? d1 : o1) * (c ? d2 : o2);
            const float2 v = table[idx];
            ax = fmaf(w, v.x, ax);
            ay = fmaf(w, v.y, ay);
        }

        // (L, N, 2) scratch layout: fully coalesced warp store (256B)
        scr[n] = make_float2(ax, ay);
    }
}

// ---------------------------------------------------------------------------
// Kernel 2: (L, N, 2) -> (N, L*2) transpose for one chunk. Reg-capped to 64
// (launch_bounds occupancy hint) so a transpose CTA can co-reside with a k1
// CTA on the same SM (smem 128+66=194KB, regs 47K+16K=63K, thr 1280).
// ---------------------------------------------------------------------------
__global__ __launch_bounds__(TTHREADS, 4)
void transpose_kernel(float* __restrict__ out, int nbase)
{
    __shared__ float2 tile[LVLS][TPITCH];   // 16 x 514 x 8B = 65.8KB

    const int n0 = nbase + blockIdx.x * TPTS;
    const int t  = threadIdx.x;

    // Load: thread t fetches points (n0+2t, n0+2t+1) for all 16 levels.
    const float4* scr4 = (const float4*)g_scr;
    #pragma unroll
    for (int l = 0; l < LVLS; ++l) {
        const float4 v = scr4[(size_t)l * (NPTS / 2) + (n0 >> 1) + t];
        *(float4*)&tile[l][2 * t] = v;      // contiguous STS.128, conflict-free
    }
    __syncthreads();

    // Store: q = float4-slot within row (pair of levels), rows p advance 32/iter.
    const int q  = t & 7;
    const int pr = t >> 3;                  // 0..31
    float4* out4 = (float4*)out;
    #pragma unroll
    for (int i = 0; i < TPTS / 32; ++i) {
        const int p = i * 32 + pr;
        const float2 a = tile[2 * q][p];
        const float2 b = tile[2 * q + 1][p];
        out4[(size_t)(n0 + p) * (LVLS / 2) + q] = make_float4(a.x, a.y, b.x, b.y);
    }
}

extern "C" void kernel_launch(void* const* d_in, const int* in_sizes, int n_in,
                              void* d_out, int out_size)
{
    const float* x;
    const float* emb;
    if (in_sizes[0] == NPTS * 3) {
        x = (const float*)d_in[0];
        emb = (const float*)d_in[1];
    } else {
        x = (const float*)d_in[1];
        emb = (const float*)d_in[0];
    }
    float* out = (float*)d_out;

    cudaFuncSetAttribute(hash_enc_kernel,
                         cudaFuncAttributeMaxDynamicSharedMemorySize,
                         TSIZE * 2 * (int)sizeof(float));

    // Side stream + events for the in-graph pipeline. Created once (first call
    // is the uncaptured correctness run); only the async launches/record/wait
    // below are captured into the graph. Non-blocking stream avoids legacy
    // implicit serialization.
    static cudaStream_t s2 = nullptr;
    static cudaEvent_t evFork[NCHUNK];
    static cudaEvent_t evJoin;
    if (s2 == nullptr) {
        cudaStreamCreateWithFlags(&s2, cudaStreamNonBlocking);
        for (int c = 0; c < NCHUNK; ++c)
            cudaEventCreateWithFlags(&evFork[c], cudaEventDisableTiming);
        cudaEventCreateWithFlags(&evJoin, cudaEventDisableTiming);
    }

    dim3 grid(CTAS_PER_LVL, LVLS);   // 144 CTAs per chunk launch

    for (int c = 0; c < NCHUNK; ++c) {
        const int nbase = c * CHPTS;
        // Producer chunk on the main (capture) stream.
        hash_enc_kernel<<<grid, NTHREADS, TSIZE * 2 * sizeof(float), 0>>>(x, emb, nbase);
        // Fork: transpose of chunk c runs on s2, concurrent with chunk c+1's
        // producer. Its DRAM-drain cost overlaps k1's smem-bound compute.
        cudaEventRecord(evFork[c], 0);
        cudaStreamWaitEvent(s2, evFork[c], 0);
        transpose_kernel<<<CHPTS / TPTS, TTHREADS, 0, s2>>>(out, nbase);
    }
    // Join: main stream completes only after the last transpose.
    cudaEventRecord(evJoin, s2);
    cudaStreamWaitEvent(0, evJoin, 0);
}

// round 9
// speedup vs baseline: 1.2945x; 1.2945x over previous
#include <cuda_runtime.h>

#define LVLS 16
#define TSIZE 16384
#define NPTS 262144
#define TMASK 16383
#define PRIME1 (-1640531535)   // 2654435761 wrapped to int32
#define PRIME2 (805459861)
#define CTAS_PER_LVL 9
#define NTHREADS 1024
#define TPTS 512               // points per transpose tile
#define TTHREADS 256           // transpose block size (2 points/thread)
#define TPITCH (TPTS + 2)      // float2 pitch: 514 -> 4112B rows, 16B aligned

// Scratch in (L, N) layout of float2 — 33.5MB static device array (allowed).
__device__ float2 g_scr[(size_t)LVLS * NPTS];

// ---------------------------------------------------------------------------
// Kernel 1: hash-grid gather. One CTA per (level, point-chunk); the level's
// 128KB table lives in shared memory. Scratch stores are WRITE-THROUGH so the
// 33.5MB drains to DRAM during this (DRAM-idle, smem-bound) kernel instead of
// as dirty writebacks during the transpose.
// ---------------------------------------------------------------------------
__global__ __launch_bounds__(NTHREADS, 1)
void hash_enc_kernel(const float* __restrict__ x,
                     const float* __restrict__ emb)
{
    extern __shared__ float2 table[];   // TSIZE float2 = 128KB
    const int level = blockIdx.y;

    // Cooperative table load (float4-vectorized, coalesced)
    {
        const float4* src = (const float4*)(emb + (size_t)level * TSIZE * 2);
        float4* dst = (float4*)table;
        #pragma unroll
        for (int i = threadIdx.x; i < (TSIZE * 2) / 4; i += NTHREADS)
            dst[i] = src[i];
    }
    __syncthreads();

    // Per-level resolution: N_l = Nmin * b^l  (identical formula to the
    // passing kernel — do not perturb index-determining arithmetic)
    const float bgrow = expf((logf(512.0f) - logf(16.0f)) * (1.0f / 16.0f));
    const float scale = 16.0f * powf(bgrow, (float)level);

    float2* scr = g_scr + (size_t)level * NPTS;

    const int stride = CTAS_PER_LVL * NTHREADS;
    for (int n = blockIdx.x * NTHREADS + threadIdx.x; n < NPTS; n += stride) {
        const float x0 = x[n * 3 + 0];
        const float x1 = x[n * 3 + 1];
        const float x2 = x[n * 3 + 2];

        const float u0 = x0 * scale, u1 = x1 * scale, u2 = x2 * scale;
        const float f0 = floorf(u0), f1 = floorf(u1), f2 = floorf(u2);
        const int   i0 = (int)f0,    i1 = (int)f1,    i2 = (int)f2;
        // d = ceil-floor is 1 when frac>0, else 0 -> diff == frac either way.
        const float d0 = u0 - f0, d1 = u1 - f1, d2 = u2 - f2;
        const float o0 = 1.0f - d0, o1 = 1.0f - d1, o2 = 1.0f - d2;

        // Pre-multiplied corner hash terms (wrapping int32, matches jnp/torch)
        const int pl0 = i0;                  const int ph0 = pl0 + 1;
        const int pl1 = i1 * PRIME1;         const int ph1 = pl1 + PRIME1;
        const int pl2 = i2 * PRIME2;         const int ph2 = pl2 + PRIME2;
        // frac==0 corners carry an exactly-zero weight, so hi = lo+1 is safe.

        float ax = 0.0f, ay = 0.0f;
        #pragma unroll
        for (int k = 0; k < 8; ++k) {
            const int a = (k >> 2) & 1;     // dim0
            const int b = (k >> 1) & 1;     // dim1
            const int c = k & 1;            // dim2
            const int h = (a ? ph0 : pl0) ^ (b ? ph1 : pl1) ^ (c ? ph2 : pl2);
            const int idx = h & TMASK;      // == mod 16384 for int32
            const float w = (a ? d0 : o0) * (b ? d1 : o1) * (c ? d2 : o2);
            const float2 v = table[idx];
            ax = fmaf(w, v.x, ax);
            ay = fmaf(w, v.y, ay);
        }

        // (L, N, 2) scratch layout, coalesced 256B warp store, WRITE-THROUGH:
        // line drains to DRAM now (free — DRAM is idle here) and stays clean
        // in L2 for the transpose, so its later eviction costs no writeback.
        asm volatile("st.global.wt.v2.f32 [%0], {%1, %2};"
                     :: "l"(scr + n), "f"(ax), "f"(ay) : "memory");
    }
}

// ---------------------------------------------------------------------------
// Kernel 2: (L, N, 2) -> (N, L*2) transpose. 512-point tiles, 2 points per
// thread via float4 loads, level-major smem. Scratch reads use __ldcs
// (read-once, evict-first). Store: warp writes 4 consecutive full 128B output
// rows per STG.128 pass (512B contiguous).
// ---------------------------------------------------------------------------
__global__ __launch_bounds__(TTHREADS)
void transpose_kernel(float* __restrict__ out)
{
    __shared__ float2 tile[LVLS][TPITCH];   // 16 x 514 x 8B = 65.8KB

    const int n0 = blockIdx.x * TPTS;
    const int t  = threadIdx.x;

    // Load: thread t fetches points (n0+2t, n0+2t+1) for all 16 levels.
    const float4* scr4 = (const float4*)g_scr;
    #pragma unroll
    for (int l = 0; l < LVLS; ++l) {
        const float4 v = __ldcs(scr4 + (size_t)l * (NPTS / 2) + (n0 >> 1) + t);
        *(float4*)&tile[l][2 * t] = v;      // contiguous STS.128, conflict-free
    }
    __syncthreads();

    // Store: q = float4-slot within row (pair of levels), rows p advance 32/iter.
    const int q  = t & 7;
    const int pr = t >> 3;                  // 0..31
    float4* out4 = (float4*)out;
    #pragma unroll
    for (int i = 0; i < TPTS / 32; ++i) {
        const int p = i * 32 + pr;
        const float2 a = tile[2 * q][p];
        const float2 b = tile[2 * q + 1][p];
        out4[(size_t)(n0 + p) * (LVLS / 2) + q] = make_float4(a.x, a.y, b.x, b.y);
    }
}

extern "C" void kernel_launch(void* const* d_in, const int* in_sizes, int n_in,
                              void* d_out, int out_size)
{
    const float* x;
    const float* emb;
    if (in_sizes[0] == NPTS * 3) {
        x = (const float*)d_in[0];
        emb = (const float*)d_in[1];
    } else {
        x = (const float*)d_in[1];
        emb = (const float*)d_in[0];
    }
    float* out = (float*)d_out;

    cudaFuncSetAttribute(hash_enc_kernel,
                         cudaFuncAttributeMaxDynamicSharedMemorySize,
                         TSIZE * 2 * (int)sizeof(float));

    dim3 grid(CTAS_PER_LVL, LVLS);   // 144 CTAs = one full wave @ 1 CTA/SM
    hash_enc_kernel<<<grid, NTHREADS, TSIZE * 2 * sizeof(float)>>>(x, emb);

    transpose_kernel<<<NPTS / TPTS, TTHREADS>>>(out);
}